// round 1
// baseline (speedup 1.0000x reference)
#include <cuda_runtime.h>
#include <math.h>

// ---------------------------------------------------------------------------
// GRELEN: gumbel-softmax adjacency + 2x diffusion-GCN GRU cell
// B=16, N=1024, U=64, K=2  (reference stacks [x, Ax, Ax] due to its loop quirk)
// ---------------------------------------------------------------------------

namespace {
constexpr int Bb   = 16;
constexpr int Nn   = 1024;
constexpr int Uu   = 64;
constexpr int DU   = 128;   // 2U
constexpr int DIN  = 384;   // 2U*(K+1)
constexpr int Mrows = Bb * Nn;       // 16384
constexpr float TAU_INV = 2.0f;      // 1/0.5
constexpr float EPSc    = 1e-10f;
}

// ------------------------------ scratch (static device globals) ------------
__device__ float g_adj[(size_t)Bb * Nn * Nn];   // 64 MB
__device__ float g_rowsum[Mrows];
__device__ float g_dinv0[Mrows];                // 1/(colsum+1)
__device__ float g_dinv1[Mrows];                // 1/(rowsum+1)
__device__ float g_X1 [Mrows * DU];             // [xin | h]
__device__ float g_P  [Mrows * DU];             // adj  @ X1
__device__ float g_Q  [Mrows * DU];             // adjT @ X1
__device__ float g_XRH[Mrows * Uu];             // r*h (new cols of X2)
__device__ float g_P2 [Mrows * Uu];             // adj  @ (r*h)
__device__ float g_Q2 [Mrows * Uu];             // adjT @ (r*h)
__device__ float g_Ug [Mrows * Uu];             // update gate u
__device__ float g_W1cat[DU * DIN];             // [Wx0+Wx1 | Wa0 | Wa1]
__device__ float g_Wccat[Uu * DIN];             // [Wcx0+Wcx1 | Wca0 | Wca1]
__device__ float g_b1s[DU];
__device__ float g_bcs[Uu];

__device__ __forceinline__ float4 ld4(const float* p) { return *reinterpret_cast<const float4*>(p); }
__device__ __forceinline__ void   st4(float* p, float4 v) { *reinterpret_cast<float4*>(p) = v; }
__device__ __forceinline__ float sigm(float x) { return 1.0f / (1.0f + expf(-x)); }

// ------------------------------ weight folding -----------------------------
// y = [x,Ax,Ax] @ W.T  =>  chunk0 weight W[:,3f], chunk1/2 weight W[:,3f+1]+W[:,3f+2]
__global__ void k_prep(const float* __restrict__ W0, const float* __restrict__ b0,
                       const float* __restrict__ W1, const float* __restrict__ b1,
                       const float* __restrict__ Wc0, const float* __restrict__ bc0,
                       const float* __restrict__ Wc1, const float* __restrict__ bc1) {
    int t = blockIdx.x * blockDim.x + threadIdx.x;
    int stride = gridDim.x * blockDim.x;
    for (int idx = t; idx < DU * DIN; idx += stride) {
        int o = idx / DIN, k = idx % DIN;
        float v;
        if (k < DU)            v = W0[o*DIN + 3*k]     + W1[o*DIN + 3*k];
        else if (k < 2*DU)   { int f = k - DU;   v = W0[o*DIN + 3*f+1] + W0[o*DIN + 3*f+2]; }
        else                 { int f = k - 2*DU; v = W1[o*DIN + 3*f+1] + W1[o*DIN + 3*f+2]; }
        g_W1cat[idx] = v;
    }
    for (int idx = t; idx < Uu * DIN; idx += stride) {
        int o = idx / DIN, k = idx % DIN;
        float v;
        if (k < DU)            v = Wc0[o*DIN + 3*k]     + Wc1[o*DIN + 3*k];
        else if (k < 2*DU)   { int f = k - DU;   v = Wc0[o*DIN + 3*f+1] + Wc0[o*DIN + 3*f+2]; }
        else                 { int f = k - 2*DU; v = Wc1[o*DIN + 3*f+1] + Wc1[o*DIN + 3*f+2]; }
        g_Wccat[idx] = v;
    }
    if (t < DU) g_b1s[t] = b0[t] + b1[t];
    if (t < Uu) g_bcs[t] = bc0[t] + bc1[t];
}

// ------------------------------ adjacency + row sums -----------------------
// adj = sigmoid(((l0+n0)-(l1+n1))/tau); one block per (b,i) row
__global__ void k_adj(const float2* __restrict__ logits, const float2* __restrict__ un) {
    int b = blockIdx.y, i = blockIdx.x, t = threadIdx.x;
    size_t base = (size_t)(b * Nn + i) * Nn;
    float s = 0.0f;
    for (int j = t; j < Nn; j += 256) {
        float2 l = logits[base + j];
        float2 u = un[base + j];
        float n0 = -logf(EPSc - logf(u.x + EPSc));
        float n1 = -logf(EPSc - logf(u.y + EPSc));
        float z  = ((l.x + n0) - (l.y + n1)) * TAU_INV;
        float p  = sigm(z);
        g_adj[base + j] = p;
        s += p;
    }
    #pragma unroll
    for (int o = 16; o; o >>= 1) s += __shfl_down_sync(0xffffffffu, s, o);
    __shared__ float red[8];
    if ((t & 31) == 0) red[t >> 5] = s;
    __syncthreads();
    if (t == 0) {
        float tot = 0.0f;
        #pragma unroll
        for (int w = 0; w < 8; w++) tot += red[w];
        g_rowsum[b * Nn + i] = tot;
    }
}

// ------------------------------ column sums -> dinv ------------------------
__global__ void k_colsum() {
    int b = blockIdx.y;
    int j = blockIdx.x * 256 + threadIdx.x;
    size_t base = (size_t)b * Nn * Nn + j;
    float s = 0.0f;
    #pragma unroll 4
    for (int i = 0; i < Nn; i++) s += g_adj[base + (size_t)i * Nn];
    g_dinv0[b * Nn + j] = 1.0f / (s + 1.0f);
    g_dinv1[b * Nn + j] = 1.0f / (g_rowsum[b * Nn + j] + 1.0f);
}

// ------------------------------ X1 = [xin | h] -----------------------------
__global__ void k_buildX1(const float* __restrict__ inp, const float* __restrict__ hx) {
    int idx = blockIdx.x * 256 + threadIdx.x;      // over Mrows*DU
    int f = idx & (DU - 1);
    int row = idx >> 7;
    g_X1[idx] = (f < Uu) ? inp[row * Uu + f] : hx[row * Uu + (f - Uu)];
}

// ------------------------------ big batched GEMM ---------------------------
// PHASE 1: P/Q (16 x [1024x1024]@[1024x128]) from X1
// PHASE 2: P2/Q2 ([...x64]) from XRH (only the new columns of X2)
// grid: (Nn/128, 2[trans], Bb), 256 threads, 128xBN tile, BK=16, double buffered
template <int PHASE>
__global__ __launch_bounds__(256) void k_gemm_big() {
    constexpr int BN = (PHASE == 1) ? DU : Uu;
    constexpr int TN = BN / 16;
    constexpr int BM = 128, BK = 16;
    const int b = blockIdx.z, trans = blockIdx.y;
    const int m0 = blockIdx.x * BM;
    const float* A = g_adj + (size_t)b * Nn * Nn;
    const float* X = ((PHASE == 1) ? g_X1 : g_XRH) + (size_t)b * Nn * BN;
    float* C = ((PHASE == 1) ? (trans ? g_Q : g_P) : (trans ? g_Q2 : g_P2)) + (size_t)b * Nn * BN;

    __shared__ float As[2][BK][BM + 4];
    __shared__ float Bs[2][BK][BN];

    const int tid = threadIdx.x;
    const int tx = tid & 15, ty = tid >> 4;

    float acc[8][TN];
    #pragma unroll
    for (int i = 0; i < 8; i++)
        #pragma unroll
        for (int j = 0; j < TN; j++) acc[i][j] = 0.0f;

    float4 pa0, pa1, pb0, pb1;

    auto loadA = [&](int k0) {
        if (!trans) {
            int r = tid >> 2, c = (tid & 3) * 4;
            pa0 = ld4(&A[(size_t)(m0 + r)      * Nn + k0 + c]);
            pa1 = ld4(&A[(size_t)(m0 + r + 64) * Nn + k0 + c]);
        } else {
            int k = tid >> 5, c = (tid & 31) * 4;
            pa0 = ld4(&A[(size_t)(k0 + k)     * Nn + m0 + c]);
            pa1 = ld4(&A[(size_t)(k0 + k + 8) * Nn + m0 + c]);
        }
    };
    auto loadB = [&](int k0) {
        if (BN == 128) {
            int k = tid >> 5, c = (tid & 31) * 4;
            pb0 = ld4(&X[(k0 + k) * BN + c]);
            pb1 = ld4(&X[(k0 + k + 8) * BN + c]);
        } else {
            int k = tid >> 4, c = (tid & 15) * 4;
            pb0 = ld4(&X[(k0 + k) * BN + c]);
        }
    };
    auto storeA = [&](int s) {
        if (!trans) {
            int r = tid >> 2, c = (tid & 3) * 4;
            As[s][c+0][r] = pa0.x; As[s][c+1][r] = pa0.y; As[s][c+2][r] = pa0.z; As[s][c+3][r] = pa0.w;
            As[s][c+0][r+64] = pa1.x; As[s][c+1][r+64] = pa1.y; As[s][c+2][r+64] = pa1.z; As[s][c+3][r+64] = pa1.w;
        } else {
            int k = tid >> 5, c = (tid & 31) * 4;
            st4(&As[s][k][c], pa0);
            st4(&As[s][k + 8][c], pa1);
        }
    };
    auto storeB = [&](int s) {
        if (BN == 128) {
            int k = tid >> 5, c = (tid & 31) * 4;
            st4(&Bs[s][k][c], pb0);
            st4(&Bs[s][k + 8][c], pb1);
        } else {
            int k = tid >> 4, c = (tid & 15) * 4;
            st4(&Bs[s][k][c], pb0);
        }
    };

    loadA(0); loadB(0); storeA(0); storeB(0);
    __syncthreads();

    int s = 0;
    constexpr int NT = Nn / BK;   // 64
    for (int kt = 0; kt < NT; kt++) {
        bool has = (kt + 1 < NT);
        if (has) { loadA((kt + 1) * BK); loadB((kt + 1) * BK); }
        #pragma unroll
        for (int kk = 0; kk < BK; kk++) {
            float a[8], bb[TN];
            *reinterpret_cast<float4*>(&a[0]) = ld4(&As[s][kk][ty * 8]);
            *reinterpret_cast<float4*>(&a[4]) = ld4(&As[s][kk][ty * 8 + 4]);
            *reinterpret_cast<float4*>(&bb[0]) = ld4(&Bs[s][kk][tx * TN]);
            if (TN == 8) *reinterpret_cast<float4*>(&bb[4]) = ld4(&Bs[s][kk][tx * TN + 4]);
            #pragma unroll
            for (int i = 0; i < 8; i++)
                #pragma unroll
                for (int j = 0; j < TN; j++) acc[i][j] += a[i] * bb[j];
        }
        if (has) { storeA(s ^ 1); storeB(s ^ 1); }
        __syncthreads();
        s ^= 1;
    }

    #pragma unroll
    for (int i = 0; i < 8; i++) {
        size_t row = m0 + ty * 8 + i;
        st4(&C[row * BN + tx * TN], make_float4(acc[i][0], acc[i][1], acc[i][2], acc[i][3]));
        if (TN == 8)
            st4(&C[row * BN + tx * TN + 4], make_float4(acc[i][4], acc[i][5], acc[i][6], acc[i][7]));
    }
}

// ------------------------------ small GEMM 1 -------------------------------
// value = sigmoid( Z1 @ W1cat.T + b ), Z1 = [X1 | dinv0*(P+X1) | dinv1*(Q+X1)]
// M=16384, N=128, K=384.  Emits r*h (XRH) and u (Ug).
__global__ __launch_bounds__(256) void k_sgemm1(const float* __restrict__ hx) {
    constexpr int BM = 64, BN = 128, BK = 16, TM = 4, TN = 8;
    const int m0 = blockIdx.x * BM;
    const int tid = threadIdx.x, tx = tid & 15, ty = tid >> 4;
    __shared__ float As[2][BK][BM + 4];
    __shared__ float Bs[2][BK][BN + 4];
    float acc[TM][TN];
    #pragma unroll
    for (int i = 0; i < TM; i++)
        #pragma unroll
        for (int j = 0; j < TN; j++) acc[i][j] = 0.0f;

    float4 pa, pb0, pb1;

    auto loadA = [&](int k0) {
        int chunk = k0 >> 7;
        int f = (k0 & 127) + (tid & 3) * 4;
        int row = m0 + (tid >> 2);
        float4 x = ld4(&g_X1[row * DU + f]);
        if (chunk == 0) pa = x;
        else if (chunk == 1) {
            float4 p = ld4(&g_P[row * DU + f]);
            float d = g_dinv0[row];
            pa = make_float4(d*(p.x+x.x), d*(p.y+x.y), d*(p.z+x.z), d*(p.w+x.w));
        } else {
            float4 q = ld4(&g_Q[row * DU + f]);
            float d = g_dinv1[row];
            pa = make_float4(d*(q.x+x.x), d*(q.y+x.y), d*(q.z+x.z), d*(q.w+x.w));
        }
    };
    auto loadB = [&](int k0) {
        int o = tid >> 2, c = (tid & 3) * 4;
        pb0 = ld4(&g_W1cat[o * DIN + k0 + c]);
        pb1 = ld4(&g_W1cat[(o + 64) * DIN + k0 + c]);
    };
    auto storeA = [&](int s) {
        int r = tid >> 2, c = (tid & 3) * 4;
        As[s][c+0][r] = pa.x; As[s][c+1][r] = pa.y; As[s][c+2][r] = pa.z; As[s][c+3][r] = pa.w;
    };
    auto storeB = [&](int s) {
        int o = tid >> 2, c = (tid & 3) * 4;
        Bs[s][c+0][o] = pb0.x; Bs[s][c+1][o] = pb0.y; Bs[s][c+2][o] = pb0.z; Bs[s][c+3][o] = pb0.w;
        Bs[s][c+0][o+64] = pb1.x; Bs[s][c+1][o+64] = pb1.y; Bs[s][c+2][o+64] = pb1.z; Bs[s][c+3][o+64] = pb1.w;
    };

    loadA(0); loadB(0); storeA(0); storeB(0);
    __syncthreads();
    int s = 0;
    constexpr int NT = DIN / BK;   // 24
    for (int kt = 0; kt < NT; kt++) {
        bool has = (kt + 1 < NT);
        if (has) { loadA((kt + 1) * BK); loadB((kt + 1) * BK); }
        #pragma unroll
        for (int kk = 0; kk < BK; kk++) {
            float a[TM], bb[TN];
            *reinterpret_cast<float4*>(&a[0])  = ld4(&As[s][kk][ty * TM]);
            *reinterpret_cast<float4*>(&bb[0]) = ld4(&Bs[s][kk][tx * TN]);
            *reinterpret_cast<float4*>(&bb[4]) = ld4(&Bs[s][kk][tx * TN + 4]);
            #pragma unroll
            for (int i = 0; i < TM; i++)
                #pragma unroll
                for (int j = 0; j < TN; j++) acc[i][j] += a[i] * bb[j];
        }
        if (has) { storeA(s ^ 1); storeB(s ^ 1); }
        __syncthreads();
        s ^= 1;
    }

    #pragma unroll
    for (int i = 0; i < TM; i++) {
        int row = m0 + ty * TM + i;
        #pragma unroll
        for (int j = 0; j < TN; j++) {
            int o = tx * TN + j;
            float v = sigm(acc[i][j] + g_b1s[o]);
            if (o < Uu) g_XRH[row * Uu + o] = v * hx[row * Uu + o];   // r*h
            else        g_Ug[row * Uu + (o - Uu)] = v;                // u
        }
    }
}

// ------------------------------ small GEMM 2 + final state -----------------
// c = tanh( Z2 @ Wccat.T + bc );  out = u*h + (1-u)*c
// Z2 chunk0 = [xin | r*h]; chunk1 = dinv0*((P|P2)+Z2c0); chunk2 = dinv1*((Q|Q2)+Z2c0)
__global__ __launch_bounds__(256) void k_sgemm2(const float* __restrict__ inp,
                                                const float* __restrict__ hx,
                                                float* __restrict__ out) {
    constexpr int BM = 64, BN = 64, BK = 16, TM = 4, TN = 4;
    const int m0 = blockIdx.x * BM;
    const int tid = threadIdx.x, tx = tid & 15, ty = tid >> 4;
    __shared__ float As[2][BK][BM + 4];
    __shared__ float Bs[2][BK][BN + 4];
    float acc[TM][TN];
    #pragma unroll
    for (int i = 0; i < TM; i++)
        #pragma unroll
        for (int j = 0; j < TN; j++) acc[i][j] = 0.0f;

    float4 pa, pb;

    auto loadX2 = [&](int row, int f) -> float4 {
        return (f < Uu) ? ld4(&inp[row * Uu + f]) : ld4(&g_XRH[row * Uu + f - Uu]);
    };
    auto loadA = [&](int k0) {
        int chunk = k0 >> 7;
        int f = (k0 & 127) + (tid & 3) * 4;
        int row = m0 + (tid >> 2);
        float4 x = loadX2(row, f);
        if (chunk == 0) pa = x;
        else if (chunk == 1) {
            float4 p = (f < Uu) ? ld4(&g_P[row * DU + f]) : ld4(&g_P2[row * Uu + f - Uu]);
            float d = g_dinv0[row];
            pa = make_float4(d*(p.x+x.x), d*(p.y+x.y), d*(p.z+x.z), d*(p.w+x.w));
        } else {
            float4 q = (f < Uu) ? ld4(&g_Q[row * DU + f]) : ld4(&g_Q2[row * Uu + f - Uu]);
            float d = g_dinv1[row];
            pa = make_float4(d*(q.x+x.x), d*(q.y+x.y), d*(q.z+x.z), d*(q.w+x.w));
        }
    };
    auto loadB = [&](int k0) {
        int o = tid >> 2, c = (tid & 3) * 4;
        pb = ld4(&g_Wccat[o * DIN + k0 + c]);
    };
    auto storeA = [&](int s) {
        int r = tid >> 2, c = (tid & 3) * 4;
        As[s][c+0][r] = pa.x; As[s][c+1][r] = pa.y; As[s][c+2][r] = pa.z; As[s][c+3][r] = pa.w;
    };
    auto storeB = [&](int s) {
        int o = tid >> 2, c = (tid & 3) * 4;
        Bs[s][c+0][o] = pb.x; Bs[s][c+1][o] = pb.y; Bs[s][c+2][o] = pb.z; Bs[s][c+3][o] = pb.w;
    };

    loadA(0); loadB(0); storeA(0); storeB(0);
    __syncthreads();
    int s = 0;
    constexpr int NT = DIN / BK;
    for (int kt = 0; kt < NT; kt++) {
        bool has = (kt + 1 < NT);
        if (has) { loadA((kt + 1) * BK); loadB((kt + 1) * BK); }
        #pragma unroll
        for (int kk = 0; kk < BK; kk++) {
            float a[TM], bb[TN];
            *reinterpret_cast<float4*>(&a[0])  = ld4(&As[s][kk][ty * TM]);
            *reinterpret_cast<float4*>(&bb[0]) = ld4(&Bs[s][kk][tx * TN]);
            #pragma unroll
            for (int i = 0; i < TM; i++)
                #pragma unroll
                for (int j = 0; j < TN; j++) acc[i][j] += a[i] * bb[j];
        }
        if (has) { storeA(s ^ 1); storeB(s ^ 1); }
        __syncthreads();
        s ^= 1;
    }

    #pragma unroll
    for (int i = 0; i < TM; i++) {
        int row = m0 + ty * TM + i;
        #pragma unroll
        for (int j = 0; j < TN; j++) {
            int o = tx * TN + j;
            float c = tanhf(acc[i][j] + g_bcs[o]);
            float u = g_Ug[row * Uu + o];
            float h = hx[row * Uu + o];
            out[row * Uu + o] = u * h + (1.0f - u) * c;
        }
    }
}

// ------------------------------ launch -------------------------------------
extern "C" void kernel_launch(void* const* d_in, const int* in_sizes, int n_in,
                              void* d_out, int out_size) {
    (void)in_sizes; (void)n_in; (void)out_size;
    const float* logits = (const float*)d_in[0];
    const float* u_noise = (const float*)d_in[1];
    const float* inputs = (const float*)d_in[2];
    const float* hx = (const float*)d_in[3];
    const float* W0 = (const float*)d_in[4];
    const float* b0 = (const float*)d_in[5];
    const float* W1 = (const float*)d_in[6];
    const float* b1 = (const float*)d_in[7];
    const float* Wc0 = (const float*)d_in[8];
    const float* bc0 = (const float*)d_in[9];
    const float* Wc1 = (const float*)d_in[10];
    const float* bc1 = (const float*)d_in[11];
    float* out = (float*)d_out;

    k_prep<<<64, 256>>>(W0, b0, W1, b1, Wc0, bc0, Wc1, bc1);
    k_adj<<<dim3(Nn, Bb), 256>>>((const float2*)logits, (const float2*)u_noise);
    k_colsum<<<dim3(Nn / 256, Bb), 256>>>();
    k_buildX1<<<(Mrows * DU) / 256, 256>>>(inputs, hx);
    k_gemm_big<1><<<dim3(Nn / 128, 2, Bb), 256>>>();
    k_sgemm1<<<Mrows / 64, 256>>>(hx);
    k_gemm_big<2><<<dim3(Nn / 128, 2, Bb), 256>>>();
    k_sgemm2<<<Mrows / 64, 256>>>(inputs, hx, out);
}

// round 3
// speedup vs baseline: 1.3611x; 1.3611x over previous
#include <cuda_runtime.h>
#include <math.h>

// ---------------------------------------------------------------------------
// GRELEN: gumbel-softmax adjacency + 2x diffusion-GCN GRU cell
// B=16, N=1024, U=64, K=2  (reference stacks [x, Ax, Ax] due to its loop quirk)
// R3: fix tf32 cvt (b32 dst reg); big batched GEMMs on tensor cores
// ---------------------------------------------------------------------------

namespace {
constexpr int Bb   = 16;
constexpr int Nn   = 1024;
constexpr int Uu   = 64;
constexpr int DU   = 128;   // 2U
constexpr int DIN  = 384;   // 2U*(K+1)
constexpr int Mrows = Bb * Nn;       // 16384
constexpr float TAU_INV = 2.0f;      // 1/0.5
constexpr float EPSc    = 1e-10f;
}

// ------------------------------ scratch (static device globals) ------------
__device__ float g_adj[(size_t)Bb * Nn * Nn];   // 64 MB
__device__ float g_rowsum[Mrows];
__device__ float g_dinv0[Mrows];                // 1/(colsum+1)
__device__ float g_dinv1[Mrows];                // 1/(rowsum+1)
__device__ float g_X1 [Mrows * DU];             // [xin | h]
__device__ float g_P  [Mrows * DU];             // adj  @ X1
__device__ float g_Q  [Mrows * DU];             // adjT @ X1
__device__ float g_XRH[Mrows * Uu];             // r*h (new cols of X2)
__device__ float g_P2 [Mrows * Uu];             // adj  @ (r*h)
__device__ float g_Q2 [Mrows * Uu];             // adjT @ (r*h)
__device__ float g_Ug [Mrows * Uu];             // update gate u
__device__ float g_W1cat[DU * DIN];             // [Wx0+Wx1 | Wa0 | Wa1]
__device__ float g_Wccat[Uu * DIN];             // [Wcx0+Wcx1 | Wca0 | Wca1]
__device__ float g_b1s[DU];
__device__ float g_bcs[Uu];

__device__ __forceinline__ float4 ld4(const float* p) { return *reinterpret_cast<const float4*>(p); }
__device__ __forceinline__ void   st4(float* p, float4 v) { *reinterpret_cast<float4*>(p) = v; }
__device__ __forceinline__ float sigm(float x) { return 1.0f / (1.0f + expf(-x)); }

__device__ __forceinline__ float to_tf32(float x) {
    unsigned u;
    asm("cvt.rna.tf32.f32 %0, %1;" : "=r"(u) : "f"(x));
    return __uint_as_float(u);
}
__device__ __forceinline__ float4 to_tf32_4(float4 v) {
    v.x = to_tf32(v.x); v.y = to_tf32(v.y); v.z = to_tf32(v.z); v.w = to_tf32(v.w);
    return v;
}

__device__ __forceinline__ void mma_tf32(float (&d)[4], const float a0, const float a1,
                                         const float a2, const float a3,
                                         const float b0, const float b1) {
    asm volatile(
        "mma.sync.aligned.m16n8k8.row.col.f32.tf32.tf32.f32 "
        "{%0,%1,%2,%3}, {%4,%5,%6,%7}, {%8,%9}, {%0,%1,%2,%3};\n"
        : "+f"(d[0]), "+f"(d[1]), "+f"(d[2]), "+f"(d[3])
        : "r"(__float_as_uint(a0)), "r"(__float_as_uint(a1)),
          "r"(__float_as_uint(a2)), "r"(__float_as_uint(a3)),
          "r"(__float_as_uint(b0)), "r"(__float_as_uint(b1)));
}

// ------------------------------ weight folding -----------------------------
__global__ void k_prep(const float* __restrict__ W0, const float* __restrict__ b0,
                       const float* __restrict__ W1, const float* __restrict__ b1,
                       const float* __restrict__ Wc0, const float* __restrict__ bc0,
                       const float* __restrict__ Wc1, const float* __restrict__ bc1) {
    int t = blockIdx.x * blockDim.x + threadIdx.x;
    int stride = gridDim.x * blockDim.x;
    for (int idx = t; idx < DU * DIN; idx += stride) {
        int o = idx / DIN, k = idx % DIN;
        float v;
        if (k < DU)            v = W0[o*DIN + 3*k]     + W1[o*DIN + 3*k];
        else if (k < 2*DU)   { int f = k - DU;   v = W0[o*DIN + 3*f+1] + W0[o*DIN + 3*f+2]; }
        else                 { int f = k - 2*DU; v = W1[o*DIN + 3*f+1] + W1[o*DIN + 3*f+2]; }
        g_W1cat[idx] = v;
    }
    for (int idx = t; idx < Uu * DIN; idx += stride) {
        int o = idx / DIN, k = idx % DIN;
        float v;
        if (k < DU)            v = Wc0[o*DIN + 3*k]     + Wc1[o*DIN + 3*k];
        else if (k < 2*DU)   { int f = k - DU;   v = Wc0[o*DIN + 3*f+1] + Wc0[o*DIN + 3*f+2]; }
        else                 { int f = k - 2*DU; v = Wc1[o*DIN + 3*f+1] + Wc1[o*DIN + 3*f+2]; }
        g_Wccat[idx] = v;
    }
    if (t < DU) g_b1s[t] = b0[t] + b1[t];
    if (t < Uu) g_bcs[t] = bc0[t] + bc1[t];
}

// ------------------------------ adjacency + row sums -----------------------
__global__ void k_adj(const float2* __restrict__ logits, const float2* __restrict__ un) {
    int b = blockIdx.y, i = blockIdx.x, t = threadIdx.x;
    size_t base = (size_t)(b * Nn + i) * Nn;
    float s = 0.0f;
    for (int j = t; j < Nn; j += 256) {
        float2 l = logits[base + j];
        float2 u = un[base + j];
        float n0 = -logf(EPSc - logf(u.x + EPSc));
        float n1 = -logf(EPSc - logf(u.y + EPSc));
        float z  = ((l.x + n0) - (l.y + n1)) * TAU_INV;
        float p  = sigm(z);
        g_adj[base + j] = p;
        s += p;
    }
    #pragma unroll
    for (int o = 16; o; o >>= 1) s += __shfl_down_sync(0xffffffffu, s, o);
    __shared__ float red[8];
    if ((t & 31) == 0) red[t >> 5] = s;
    __syncthreads();
    if (t == 0) {
        float tot = 0.0f;
        #pragma unroll
        for (int w = 0; w < 8; w++) tot += red[w];
        g_rowsum[b * Nn + i] = tot;
    }
}

// ------------------------------ column sums -> dinv ------------------------
__global__ void k_colsum() {
    int b = blockIdx.y;
    int j = blockIdx.x * 256 + threadIdx.x;
    size_t base = (size_t)b * Nn * Nn + j;
    float s = 0.0f;
    #pragma unroll 4
    for (int i = 0; i < Nn; i++) s += g_adj[base + (size_t)i * Nn];
    g_dinv0[b * Nn + j] = 1.0f / (s + 1.0f);
    g_dinv1[b * Nn + j] = 1.0f / (g_rowsum[b * Nn + j] + 1.0f);
}

// ------------------------------ X1 = [xin | h] -----------------------------
__global__ void k_buildX1(const float* __restrict__ inp, const float* __restrict__ hx) {
    int idx = blockIdx.x * 256 + threadIdx.x;
    int f = idx & (DU - 1);
    int row = idx >> 7;
    g_X1[idx] = (f < Uu) ? inp[row * Uu + f] : hx[row * Uu + (f - Uu)];
}

// ------------------------------ big batched GEMM (tf32 tensor cores) -------
// PHASE 1: P/Q = A(T) @ X1 (BN=128).  PHASE 2: P2/Q2 = A(T) @ XRH (BN=64).
// BM=128, BK=16, 256 threads = 8 warps. tf32 rounding applied before smem store.
template <int PHASE>
__global__ __launch_bounds__(256) void k_gemm_tc() {
    constexpr int BN = (PHASE == 1) ? DU : Uu;
    constexpr int BM = 128, BK = 16;
    constexpr int wn_ = (BN == 128) ? 4 : 2;
    constexpr int wm_ = 8 / wn_;
    constexpr int mf_ = (BM / wm_) / 16;   // BN=128: 4 ; BN=64: 2
    constexpr int nf_ = (BN / wn_) / 8;    // both: 4

    const int b = blockIdx.z, trans = blockIdx.y;
    const int m0 = blockIdx.x * BM;
    const float* A = g_adj + (size_t)b * Nn * Nn;
    const float* X = ((PHASE == 1) ? g_X1 : g_XRH) + (size_t)b * Nn * BN;
    float* C = ((PHASE == 1) ? (trans ? g_Q : g_P) : (trans ? g_Q2 : g_P2)) + (size_t)b * Nn * BN;

    __shared__ float As[2][BK][BM + 8];
    __shared__ float Bs[2][BK][BN + 8];

    const int tid  = threadIdx.x;
    const int w    = tid >> 5;
    const int lane = tid & 31;
    const int g4   = lane >> 2;   // 0..7
    const int t4   = lane & 3;    // 0..3
    const int warp_m = (w % wm_) * (BM / wm_);
    const int warp_n = (w / wm_) * (BN / wn_);

    float acc[mf_][nf_][4];
    #pragma unroll
    for (int i = 0; i < mf_; i++)
        #pragma unroll
        for (int j = 0; j < nf_; j++)
            #pragma unroll
            for (int r = 0; r < 4; r++) acc[i][j][r] = 0.0f;

    float4 pa0, pa1, pb0, pb1;

    auto loadA = [&](int k0) {
        if (!trans) {
            int r = tid >> 2, c = (tid & 3) * 4;
            pa0 = to_tf32_4(ld4(&A[(size_t)(m0 + r)      * Nn + k0 + c]));
            pa1 = to_tf32_4(ld4(&A[(size_t)(m0 + r + 64) * Nn + k0 + c]));
        } else {
            int k = tid >> 5, c = (tid & 31) * 4;
            pa0 = to_tf32_4(ld4(&A[(size_t)(k0 + k)     * Nn + m0 + c]));
            pa1 = to_tf32_4(ld4(&A[(size_t)(k0 + k + 8) * Nn + m0 + c]));
        }
    };
    auto loadB = [&](int k0) {
        if (BN == 128) {
            int k = tid >> 5, c = (tid & 31) * 4;
            pb0 = to_tf32_4(ld4(&X[(k0 + k) * BN + c]));
            pb1 = to_tf32_4(ld4(&X[(k0 + k + 8) * BN + c]));
        } else {
            int k = tid >> 4, c = (tid & 15) * 4;
            pb0 = to_tf32_4(ld4(&X[(k0 + k) * BN + c]));
        }
    };
    auto storeA = [&](int s) {
        if (!trans) {
            int r = tid >> 2, c = (tid & 3) * 4;
            As[s][c+0][r] = pa0.x; As[s][c+1][r] = pa0.y; As[s][c+2][r] = pa0.z; As[s][c+3][r] = pa0.w;
            As[s][c+0][r+64] = pa1.x; As[s][c+1][r+64] = pa1.y; As[s][c+2][r+64] = pa1.z; As[s][c+3][r+64] = pa1.w;
        } else {
            int k = tid >> 5, c = (tid & 31) * 4;
            st4(&As[s][k][c], pa0);
            st4(&As[s][k + 8][c], pa1);
        }
    };
    auto storeB = [&](int s) {
        if (BN == 128) {
            int k = tid >> 5, c = (tid & 31) * 4;
            st4(&Bs[s][k][c], pb0);
            st4(&Bs[s][k + 8][c], pb1);
        } else {
            int k = tid >> 4, c = (tid & 15) * 4;
            st4(&Bs[s][k][c], pb0);
        }
    };

    loadA(0); loadB(0); storeA(0); storeB(0);
    __syncthreads();

    int s = 0;
    constexpr int NT = Nn / BK;   // 64
    for (int kt = 0; kt < NT; kt++) {
        bool has = (kt + 1 < NT);
        if (has) { loadA((kt + 1) * BK); loadB((kt + 1) * BK); }
        #pragma unroll
        for (int ks = 0; ks < BK / 8; ks++) {
            float a[mf_][4];
            #pragma unroll
            for (int mf = 0; mf < mf_; mf++) {
                int row = warp_m + mf * 16 + g4;
                a[mf][0] = As[s][ks*8 + t4    ][row];
                a[mf][1] = As[s][ks*8 + t4    ][row + 8];
                a[mf][2] = As[s][ks*8 + t4 + 4][row];
                a[mf][3] = As[s][ks*8 + t4 + 4][row + 8];
            }
            #pragma unroll
            for (int nf = 0; nf < nf_; nf++) {
                int col = warp_n + nf * 8 + g4;
                float b0 = Bs[s][ks*8 + t4    ][col];
                float b1 = Bs[s][ks*8 + t4 + 4][col];
                #pragma unroll
                for (int mf = 0; mf < mf_; mf++)
                    mma_tf32(acc[mf][nf], a[mf][0], a[mf][1], a[mf][2], a[mf][3], b0, b1);
            }
        }
        if (has) { storeA(s ^ 1); storeB(s ^ 1); }
        __syncthreads();
        s ^= 1;
    }

    #pragma unroll
    for (int mf = 0; mf < mf_; mf++) {
        int r0 = m0 + warp_m + mf * 16 + g4;
        #pragma unroll
        for (int nf = 0; nf < nf_; nf++) {
            int cc = warp_n + nf * 8 + 2 * t4;
            *reinterpret_cast<float2*>(&C[(size_t)r0 * BN + cc]) =
                make_float2(acc[mf][nf][0], acc[mf][nf][1]);
            *reinterpret_cast<float2*>(&C[(size_t)(r0 + 8) * BN + cc]) =
                make_float2(acc[mf][nf][2], acc[mf][nf][3]);
        }
    }
}

// ------------------------------ small GEMM 1 (fp32, unchanged) -------------
__global__ __launch_bounds__(256) void k_sgemm1(const float* __restrict__ hx) {
    constexpr int BM = 64, BN = 128, BK = 16, TM = 4, TN = 8;
    const int m0 = blockIdx.x * BM;
    const int tid = threadIdx.x, tx = tid & 15, ty = tid >> 4;
    __shared__ float As[2][BK][BM + 4];
    __shared__ float Bs[2][BK][BN + 4];
    float acc[TM][TN];
    #pragma unroll
    for (int i = 0; i < TM; i++)
        #pragma unroll
        for (int j = 0; j < TN; j++) acc[i][j] = 0.0f;

    float4 pa, pb0, pb1;

    auto loadA = [&](int k0) {
        int chunk = k0 >> 7;
        int f = (k0 & 127) + (tid & 3) * 4;
        int row = m0 + (tid >> 2);
        float4 x = ld4(&g_X1[row * DU + f]);
        if (chunk == 0) pa = x;
        else if (chunk == 1) {
            float4 p = ld4(&g_P[row * DU + f]);
            float d = g_dinv0[row];
            pa = make_float4(d*(p.x+x.x), d*(p.y+x.y), d*(p.z+x.z), d*(p.w+x.w));
        } else {
            float4 q = ld4(&g_Q[row * DU + f]);
            float d = g_dinv1[row];
            pa = make_float4(d*(q.x+x.x), d*(q.y+x.y), d*(q.z+x.z), d*(q.w+x.w));
        }
    };
    auto loadB = [&](int k0) {
        int o = tid >> 2, c = (tid & 3) * 4;
        pb0 = ld4(&g_W1cat[o * DIN + k0 + c]);
        pb1 = ld4(&g_W1cat[(o + 64) * DIN + k0 + c]);
    };
    auto storeA = [&](int s) {
        int r = tid >> 2, c = (tid & 3) * 4;
        As[s][c+0][r] = pa.x; As[s][c+1][r] = pa.y; As[s][c+2][r] = pa.z; As[s][c+3][r] = pa.w;
    };
    auto storeB = [&](int s) {
        int o = tid >> 2, c = (tid & 3) * 4;
        Bs[s][c+0][o] = pb0.x; Bs[s][c+1][o] = pb0.y; Bs[s][c+2][o] = pb0.z; Bs[s][c+3][o] = pb0.w;
        Bs[s][c+0][o+64] = pb1.x; Bs[s][c+1][o+64] = pb1.y; Bs[s][c+2][o+64] = pb1.z; Bs[s][c+3][o+64] = pb1.w;
    };

    loadA(0); loadB(0); storeA(0); storeB(0);
    __syncthreads();
    int s = 0;
    constexpr int NT = DIN / BK;   // 24
    for (int kt = 0; kt < NT; kt++) {
        bool has = (kt + 1 < NT);
        if (has) { loadA((kt + 1) * BK); loadB((kt + 1) * BK); }
        #pragma unroll
        for (int kk = 0; kk < BK; kk++) {
            float a[TM], bb[TN];
            *reinterpret_cast<float4*>(&a[0])  = ld4(&As[s][kk][ty * TM]);
            *reinterpret_cast<float4*>(&bb[0]) = ld4(&Bs[s][kk][tx * TN]);
            *reinterpret_cast<float4*>(&bb[4]) = ld4(&Bs[s][kk][tx * TN + 4]);
            #pragma unroll
            for (int i = 0; i < TM; i++)
                #pragma unroll
                for (int j = 0; j < TN; j++) acc[i][j] += a[i] * bb[j];
        }
        if (has) { storeA(s ^ 1); storeB(s ^ 1); }
        __syncthreads();
        s ^= 1;
    }

    #pragma unroll
    for (int i = 0; i < TM; i++) {
        int row = m0 + ty * TM + i;
        #pragma unroll
        for (int j = 0; j < TN; j++) {
            int o = tx * TN + j;
            float v = sigm(acc[i][j] + g_b1s[o]);
            if (o < Uu) g_XRH[row * Uu + o] = v * hx[row * Uu + o];   // r*h
            else        g_Ug[row * Uu + (o - Uu)] = v;                // u
        }
    }
}

// ------------------------------ small GEMM 2 + final state (fp32) ----------
__global__ __launch_bounds__(256) void k_sgemm2(const float* __restrict__ inp,
                                                const float* __restrict__ hx,
                                                float* __restrict__ out) {
    constexpr int BM = 64, BN = 64, BK = 16, TM = 4, TN = 4;
    const int m0 = blockIdx.x * BM;
    const int tid = threadIdx.x, tx = tid & 15, ty = tid >> 4;
    __shared__ float As[2][BK][BM + 4];
    __shared__ float Bs[2][BK][BN + 4];
    float acc[TM][TN];
    #pragma unroll
    for (int i = 0; i < TM; i++)
        #pragma unroll
        for (int j = 0; j < TN; j++) acc[i][j] = 0.0f;

    float4 pa, pb;

    auto loadX2 = [&](int row, int f) -> float4 {
        return (f < Uu) ? ld4(&inp[row * Uu + f]) : ld4(&g_XRH[row * Uu + f - Uu]);
    };
    auto loadA = [&](int k0) {
        int chunk = k0 >> 7;
        int f = (k0 & 127) + (tid & 3) * 4;
        int row = m0 + (tid >> 2);
        float4 x = loadX2(row, f);
        if (chunk == 0) pa = x;
        else if (chunk == 1) {
            float4 p = (f < Uu) ? ld4(&g_P[row * DU + f]) : ld4(&g_P2[row * Uu + f - Uu]);
            float d = g_dinv0[row];
            pa = make_float4(d*(p.x+x.x), d*(p.y+x.y), d*(p.z+x.z), d*(p.w+x.w));
        } else {
            float4 q = (f < Uu) ? ld4(&g_Q[row * DU + f]) : ld4(&g_Q2[row * Uu + f - Uu]);
            float d = g_dinv1[row];
            pa = make_float4(d*(q.x+x.x), d*(q.y+x.y), d*(q.z+x.z), d*(q.w+x.w));
        }
    };
    auto loadB = [&](int k0) {
        int o = tid >> 2, c = (tid & 3) * 4;
        pb = ld4(&g_Wccat[o * DIN + k0 + c]);
    };
    auto storeA = [&](int s) {
        int r = tid >> 2, c = (tid & 3) * 4;
        As[s][c+0][r] = pa.x; As[s][c+1][r] = pa.y; As[s][c+2][r] = pa.z; As[s][c+3][r] = pa.w;
    };
    auto storeB = [&](int s) {
        int o = tid >> 2, c = (tid & 3) * 4;
        Bs[s][c+0][o] = pb.x; Bs[s][c+1][o] = pb.y; Bs[s][c+2][o] = pb.z; Bs[s][c+3][o] = pb.w;
    };

    loadA(0); loadB(0); storeA(0); storeB(0);
    __syncthreads();
    int s = 0;
    constexpr int NT = DIN / BK;
    for (int kt = 0; kt < NT; kt++) {
        bool has = (kt + 1 < NT);
        if (has) { loadA((kt + 1) * BK); loadB((kt + 1) * BK); }
        #pragma unroll
        for (int kk = 0; kk < BK; kk++) {
            float a[TM], bb[TN];
            *reinterpret_cast<float4*>(&a[0])  = ld4(&As[s][kk][ty * TM]);
            *reinterpret_cast<float4*>(&bb[0]) = ld4(&Bs[s][kk][tx * TN]);
            #pragma unroll
            for (int i = 0; i < TM; i++)
                #pragma unroll
                for (int j = 0; j < TN; j++) acc[i][j] += a[i] * bb[j];
        }
        if (has) { storeA(s ^ 1); storeB(s ^ 1); }
        __syncthreads();
        s ^= 1;
    }

    #pragma unroll
    for (int i = 0; i < TM; i++) {
        int row = m0 + ty * TM + i;
        #pragma unroll
        for (int j = 0; j < TN; j++) {
            int o = tx * TN + j;
            float c = tanhf(acc[i][j] + g_bcs[o]);
            float u = g_Ug[row * Uu + o];
            float h = hx[row * Uu + o];
            out[row * Uu + o] = u * h + (1.0f - u) * c;
        }
    }
}

// ------------------------------ launch -------------------------------------
extern "C" void kernel_launch(void* const* d_in, const int* in_sizes, int n_in,
                              void* d_out, int out_size) {
    (void)in_sizes; (void)n_in; (void)out_size;
    const float* logits = (const float*)d_in[0];
    const float* u_noise = (const float*)d_in[1];
    const float* inputs = (const float*)d_in[2];
    const float* hx = (const float*)d_in[3];
    const float* W0 = (const float*)d_in[4];
    const float* b0 = (const float*)d_in[5];
    const float* W1 = (const float*)d_in[6];
    const float* b1 = (const float*)d_in[7];
    const float* Wc0 = (const float*)d_in[8];
    const float* bc0 = (const float*)d_in[9];
    const float* Wc1 = (const float*)d_in[10];
    const float* bc1 = (const float*)d_in[11];
    float* out = (float*)d_out;

    k_prep<<<64, 256>>>(W0, b0, W1, b1, Wc0, bc0, Wc1, bc1);
    k_adj<<<dim3(Nn, Bb), 256>>>((const float2*)logits, (const float2*)u_noise);
    k_colsum<<<dim3(Nn / 256, Bb), 256>>>();
    k_buildX1<<<(Mrows * DU) / 256, 256>>>(inputs, hx);
    k_gemm_tc<1><<<dim3(Nn / 128, 2, Bb), 256>>>();
    k_sgemm1<<<Mrows / 64, 256>>>(hx);
    k_gemm_tc<2><<<dim3(Nn / 128, 2, Bb), 256>>>();
    k_sgemm2<<<Mrows / 64, 256>>>(inputs, hx, out);
}

// round 4
// speedup vs baseline: 2.1254x; 1.5615x over previous
#include <cuda_runtime.h>
#include <math.h>

// ---------------------------------------------------------------------------
// GRELEN: gumbel-softmax adjacency + 2x diffusion-GCN GRU cell
// B=16, N=1024, U=64, K=2  (reference stacks [x, Ax, Ax] due to its loop quirk)
// R4: cp.async 4-stage tf32 big GEMM; tf32 weight GEMMs; fast-math adjacency
// ---------------------------------------------------------------------------

namespace {
constexpr int Bb   = 16;
constexpr int Nn   = 1024;
constexpr int Uu   = 64;
constexpr int DU   = 128;   // 2U
constexpr int DIN  = 384;   // 2U*(K+1)
constexpr int Mrows = Bb * Nn;       // 16384
constexpr float EPSc = 1e-10f;
}

// ------------------------------ scratch ------------------------------------
__device__ float g_adj[(size_t)Bb * Nn * Nn];   // 64 MB
__device__ float g_rowsum[Mrows];
__device__ float g_dinv0[Mrows];
__device__ float g_dinv1[Mrows];
__device__ float g_X1 [Mrows * DU];
__device__ float g_P  [Mrows * DU];
__device__ float g_Q  [Mrows * DU];
__device__ float g_XRH[Mrows * Uu];
__device__ float g_P2 [Mrows * Uu];
__device__ float g_Q2 [Mrows * Uu];
__device__ float g_Ug [Mrows * Uu];
__device__ float g_Z  [(size_t)Mrows * DIN];    // 25 MB staging for weight GEMMs
__device__ float g_W1cat[DU * DIN];
__device__ float g_Wccat[Uu * DIN];
__device__ float g_b1s[DU];
__device__ float g_bcs[Uu];

__device__ __forceinline__ float4 ld4(const float* p) { return *reinterpret_cast<const float4*>(p); }
__device__ __forceinline__ void   st4(float* p, float4 v) { *reinterpret_cast<float4*>(p) = v; }
__device__ __forceinline__ float sigm(float x) { return 1.0f / (1.0f + expf(-x)); }

__device__ __forceinline__ void cpasync16(float* dst_smem, const float* src) {
    unsigned d = (unsigned)__cvta_generic_to_shared(dst_smem);
    asm volatile("cp.async.cg.shared.global [%0], [%1], 16;\n" :: "r"(d), "l"(src));
}
__device__ __forceinline__ void cp_commit() {
    asm volatile("cp.async.commit_group;\n" ::: "memory");
}
template <int N>
__device__ __forceinline__ void cp_wait() {
    asm volatile("cp.async.wait_group %0;\n" :: "n"(N) : "memory");
}

__device__ __forceinline__ void mma_tf32(float (&d)[4], const float a0, const float a1,
                                         const float a2, const float a3,
                                         const float b0, const float b1) {
    asm volatile(
        "mma.sync.aligned.m16n8k8.row.col.f32.tf32.tf32.f32 "
        "{%0,%1,%2,%3}, {%4,%5,%6,%7}, {%8,%9}, {%0,%1,%2,%3};\n"
        : "+f"(d[0]), "+f"(d[1]), "+f"(d[2]), "+f"(d[3])
        : "r"(__float_as_uint(a0)), "r"(__float_as_uint(a1)),
          "r"(__float_as_uint(a2)), "r"(__float_as_uint(a3)),
          "r"(__float_as_uint(b0)), "r"(__float_as_uint(b1)));
}

// ------------------------------ weight folding -----------------------------
__global__ void k_prep(const float* __restrict__ W0, const float* __restrict__ b0,
                       const float* __restrict__ W1, const float* __restrict__ b1,
                       const float* __restrict__ Wc0, const float* __restrict__ bc0,
                       const float* __restrict__ Wc1, const float* __restrict__ bc1) {
    int t = blockIdx.x * blockDim.x + threadIdx.x;
    int stride = gridDim.x * blockDim.x;
    for (int idx = t; idx < DU * DIN; idx += stride) {
        int o = idx / DIN, k = idx % DIN;
        float v;
        if (k < DU)            v = W0[o*DIN + 3*k]     + W1[o*DIN + 3*k];
        else if (k < 2*DU)   { int f = k - DU;   v = W0[o*DIN + 3*f+1] + W0[o*DIN + 3*f+2]; }
        else                 { int f = k - 2*DU; v = W1[o*DIN + 3*f+1] + W1[o*DIN + 3*f+2]; }
        g_W1cat[idx] = v;
    }
    for (int idx = t; idx < Uu * DIN; idx += stride) {
        int o = idx / DIN, k = idx % DIN;
        float v;
        if (k < DU)            v = Wc0[o*DIN + 3*k]     + Wc1[o*DIN + 3*k];
        else if (k < 2*DU)   { int f = k - DU;   v = Wc0[o*DIN + 3*f+1] + Wc0[o*DIN + 3*f+2]; }
        else                 { int f = k - 2*DU; v = Wc1[o*DIN + 3*f+1] + Wc1[o*DIN + 3*f+2]; }
        g_Wccat[idx] = v;
    }
    if (t < DU) g_b1s[t] = b0[t] + b1[t];
    if (t < Uu) g_bcs[t] = bc0[t] + bc1[t];
}

// ------------------------------ adjacency + row sums -----------------------
// n0-n1 = log(t1/t0), t_i = eps - log(u_i+eps);  z = 2*((l0-l1)+log t1-log t0)
__global__ void k_adj(const float4* __restrict__ logits4, const float4* __restrict__ un4) {
    int b = blockIdx.y, i = blockIdx.x, t = threadIdx.x;
    size_t base4 = (size_t)(b * Nn + i) * (Nn / 2);   // float4 = 2 elements
    float2* adj2 = reinterpret_cast<float2*>(g_adj + (size_t)(b * Nn + i) * Nn);
    float s = 0.0f;
    #pragma unroll
    for (int j = t; j < Nn / 2; j += 256) {
        float4 l = logits4[base4 + j];
        float4 u = un4[base4 + j];
        float t0a = EPSc - __logf(u.x + EPSc), t1a = EPSc - __logf(u.y + EPSc);
        float t0b = EPSc - __logf(u.z + EPSc), t1b = EPSc - __logf(u.w + EPSc);
        float za = 2.0f * ((l.x - l.y) + __logf(t1a) - __logf(t0a));
        float zb = 2.0f * ((l.z - l.w) + __logf(t1b) - __logf(t0b));
        float pa = __fdividef(1.0f, 1.0f + __expf(-za));
        float pb = __fdividef(1.0f, 1.0f + __expf(-zb));
        adj2[j] = make_float2(pa, pb);
        s += pa + pb;
    }
    #pragma unroll
    for (int o = 16; o; o >>= 1) s += __shfl_down_sync(0xffffffffu, s, o);
    __shared__ float red[8];
    if ((t & 31) == 0) red[t >> 5] = s;
    __syncthreads();
    if (t == 0) {
        float tot = 0.0f;
        #pragma unroll
        for (int w = 0; w < 8; w++) tot += red[w];
        g_rowsum[b * Nn + i] = tot;
    }
}

// ------------------------------ column sums -> dinv ------------------------
__global__ void k_colsum() {
    int b = blockIdx.y;
    int j = blockIdx.x * 256 + threadIdx.x;
    size_t base = (size_t)b * Nn * Nn + j;
    float s = 0.0f;
    #pragma unroll 8
    for (int i = 0; i < Nn; i++) s += g_adj[base + (size_t)i * Nn];
    g_dinv0[b * Nn + j] = 1.0f / (s + 1.0f);
    g_dinv1[b * Nn + j] = 1.0f / (g_rowsum[b * Nn + j] + 1.0f);
}

// ------------------------------ X1 = [xin | h] (float4) --------------------
__global__ void k_buildX1(const float* __restrict__ inp, const float* __restrict__ hx) {
    int idx = blockIdx.x * 256 + threadIdx.x;    // Mrows * 32 float4s
    int f4 = idx & 31;
    int row = idx >> 5;
    float4 v = (f4 < 16) ? ld4(&inp[row * Uu + f4 * 4]) : ld4(&hx[row * Uu + (f4 - 16) * 4]);
    st4(&g_X1[row * DU + f4 * 4], v);
}

// ------------------------------ big batched GEMM (tf32, cp.async x4) -------
// PHASE 1: P/Q = A(T) @ X1 (BN=128).  PHASE 2: P2/Q2 = A(T) @ XRH (BN=64).
// BM=128, BK=8, 4 stages. trans=blockIdx.y. A layout: non-trans [m][12], trans [k][136].
template <int PHASE>
__global__ __launch_bounds__(256) void k_gemm_tc() {
    constexpr int BN = (PHASE == 1) ? DU : Uu;
    constexpr int BM = 128, BK = 8, STAGES = 4;
    constexpr int ASZ = 1536;                  // floats per A stage (max of 128*12, 8*136)
    constexpr int BSTR = BN + 8;               // 136 or 72
    constexpr int BSZ = BK * BSTR;
    constexpr int wn_ = (BN == 128) ? 4 : 2;
    constexpr int wm_ = 8 / wn_;
    constexpr int mf_ = (BM / wm_) / 16;       // 4 or 2
    constexpr int nf_ = (BN / wn_) / 8;        // 4

    const int b = blockIdx.z, trans = blockIdx.y;
    const int m0 = blockIdx.x * BM;
    const float* A = g_adj + (size_t)b * Nn * Nn;
    const float* X = ((PHASE == 1) ? g_X1 : g_XRH) + (size_t)b * Nn * BN;
    float* C = ((PHASE == 1) ? (trans ? g_Q : g_P) : (trans ? g_Q2 : g_P2)) + (size_t)b * Nn * BN;

    __shared__ float As[STAGES * ASZ];
    __shared__ float Bs[STAGES * BSZ];

    const int tid  = threadIdx.x;
    const int w    = tid >> 5;
    const int lane = tid & 31;
    const int g4   = lane >> 2;
    const int t4   = lane & 3;
    const int warp_m = (w % wm_) * (BM / wm_);
    const int warp_n = (w / wm_) * (BN / wn_);

    float acc[mf_][nf_][4];
    #pragma unroll
    for (int i = 0; i < mf_; i++)
        #pragma unroll
        for (int j = 0; j < nf_; j++)
            #pragma unroll
            for (int r = 0; r < 4; r++) acc[i][j][r] = 0.0f;

    auto issue = [&](int st, int k0) {
        float* as = As + st * ASZ;
        float* bs = Bs + st * BSZ;
        if (!trans) {
            int r = tid >> 1, c = (tid & 1) * 4;                 // [m][12]
            cpasync16(&as[r * 12 + c], &A[(size_t)(m0 + r) * Nn + k0 + c]);
        } else {
            int k = tid >> 5, c = (tid & 31) * 4;                // [k][136]
            cpasync16(&as[k * 136 + c], &A[(size_t)(k0 + k) * Nn + m0 + c]);
        }
        if (BN == 128) {
            int k = tid >> 5, c = (tid & 31) * 4;
            cpasync16(&bs[k * BSTR + c], &X[(k0 + k) * BN + c]);
        } else {
            if (tid < 128) {
                int k = tid >> 4, c = (tid & 15) * 4;
                cpasync16(&bs[k * BSTR + c], &X[(k0 + k) * BN + c]);
            }
        }
        cp_commit();
    };

    constexpr int NT = Nn / BK;   // 128
    issue(0, 0); issue(1, BK); issue(2, 2 * BK);

    for (int kt = 0; kt < NT; kt++) {
        cp_wait<STAGES - 2>();
        __syncthreads();
        const int st = kt & (STAGES - 1);
        const float* as = As + st * ASZ;
        const float* bs = Bs + st * BSZ;

        float a[mf_][4];
        if (!trans) {
            #pragma unroll
            for (int mf = 0; mf < mf_; mf++) {
                int row = warp_m + mf * 16 + g4;
                a[mf][0] = as[ row      * 12 + t4    ];
                a[mf][1] = as[(row + 8) * 12 + t4    ];
                a[mf][2] = as[ row      * 12 + t4 + 4];
                a[mf][3] = as[(row + 8) * 12 + t4 + 4];
            }
        } else {
            #pragma unroll
            for (int mf = 0; mf < mf_; mf++) {
                int row = warp_m + mf * 16 + g4;
                a[mf][0] = as[ t4      * 136 + row    ];
                a[mf][1] = as[ t4      * 136 + row + 8];
                a[mf][2] = as[(t4 + 4) * 136 + row    ];
                a[mf][3] = as[(t4 + 4) * 136 + row + 8];
            }
        }
        #pragma unroll
        for (int nf = 0; nf < nf_; nf++) {
            int col = warp_n + nf * 8 + g4;
            float b0 = bs[ t4      * BSTR + col];
            float b1 = bs[(t4 + 4) * BSTR + col];
            #pragma unroll
            for (int mf = 0; mf < mf_; mf++)
                mma_tf32(acc[mf][nf], a[mf][0], a[mf][1], a[mf][2], a[mf][3], b0, b1);
        }

        if (kt + STAGES - 1 < NT) {
            issue((kt + STAGES - 1) & (STAGES - 1), (kt + STAGES - 1) * BK);
        } else {
            cp_commit();   // keep per-thread group count in lockstep for cp_wait
        }
    }

    #pragma unroll
    for (int mf = 0; mf < mf_; mf++) {
        int r0 = m0 + warp_m + mf * 16 + g4;
        #pragma unroll
        for (int nf = 0; nf < nf_; nf++) {
            int cc = warp_n + nf * 8 + 2 * t4;
            *reinterpret_cast<float2*>(&C[(size_t)r0 * BN + cc]) =
                make_float2(acc[mf][nf][0], acc[mf][nf][1]);
            *reinterpret_cast<float2*>(&C[(size_t)(r0 + 8) * BN + cc]) =
                make_float2(acc[mf][nf][2], acc[mf][nf][3]);
        }
    }
}

// ------------------------------ Z builders ---------------------------------
// Z1 = [X1 | dinv0*(P+X1) | dinv1*(Q+X1)]
__global__ void k_buildZ1() {
    int idx = blockIdx.x * 256 + threadIdx.x;    // Mrows * 32 float4s
    int f = (idx & 31) * 4;
    int row = idx >> 5;
    float4 x = ld4(&g_X1[row * DU + f]);
    float4 p = ld4(&g_P [row * DU + f]);
    float4 q = ld4(&g_Q [row * DU + f]);
    float d0 = g_dinv0[row], d1 = g_dinv1[row];
    size_t zb = (size_t)row * DIN;
    st4(&g_Z[zb + f], x);
    st4(&g_Z[zb + DU + f],     make_float4(d0*(p.x+x.x), d0*(p.y+x.y), d0*(p.z+x.z), d0*(p.w+x.w)));
    st4(&g_Z[zb + 2*DU + f],   make_float4(d1*(q.x+x.x), d1*(q.y+x.y), d1*(q.z+x.z), d1*(q.w+x.w)));
}

// Z2 = [xin|rh | dinv0*((P|P2)+c0) | dinv1*((Q|Q2)+c0)]
__global__ void k_buildZ2(const float* __restrict__ inp) {
    int idx = blockIdx.x * 256 + threadIdx.x;
    int f = (idx & 31) * 4;
    int row = idx >> 5;
    float4 x, p, q;
    if (f < Uu) {
        x = ld4(&inp  [row * Uu + f]);
        p = ld4(&g_P  [row * DU + f]);
        q = ld4(&g_Q  [row * DU + f]);
    } else {
        x = ld4(&g_XRH[row * Uu + f - Uu]);
        p = ld4(&g_P2 [row * Uu + f - Uu]);
        q = ld4(&g_Q2 [row * Uu + f - Uu]);
    }
    float d0 = g_dinv0[row], d1 = g_dinv1[row];
    size_t zb = (size_t)row * DIN;
    st4(&g_Z[zb + f], x);
    st4(&g_Z[zb + DU + f],   make_float4(d0*(p.x+x.x), d0*(p.y+x.y), d0*(p.z+x.z), d0*(p.w+x.w)));
    st4(&g_Z[zb + 2*DU + f], make_float4(d1*(q.x+x.x), d1*(q.y+x.y), d1*(q.z+x.z), d1*(q.w+x.w)));
}

// ------------------------------ weight GEMMs (tf32, cp.async x3) -----------
// WHICH=1: sigmoid(Z @ W1cat^T + b1s) -> XRH (= r*h), Ug.   BN=128
// WHICH=2: tanh(Z @ Wccat^T + bcs) -> out = u*h + (1-u)*c.  BN=64
template <int WHICH>
__global__ __launch_bounds__(256) void k_wgemm(const float* __restrict__ hx,
                                               float* __restrict__ out) {
    constexpr int BN = (WHICH == 1) ? DU : Uu;
    constexpr int BM = 128, BK = 8, STAGES = 3;
    constexpr int ASZ = BM * 12;               // [m][12]
    constexpr int WSZ = BN * 12;               // [n][12]
    constexpr int wn_ = (BN == 128) ? 4 : 2;
    constexpr int wm_ = 8 / wn_;
    constexpr int mf_ = (BM / wm_) / 16;
    constexpr int nf_ = (BN / wn_) / 8;

    const int m0 = blockIdx.x * BM;
    const float* Wc = (WHICH == 1) ? g_W1cat : g_Wccat;

    __shared__ float As[STAGES * ASZ];
    __shared__ float Ws[STAGES * WSZ];

    const int tid  = threadIdx.x;
    const int w    = tid >> 5;
    const int lane = tid & 31;
    const int g4   = lane >> 2;
    const int t4   = lane & 3;
    const int warp_m = (w % wm_) * (BM / wm_);
    const int warp_n = (w / wm_) * (BN / wn_);

    float acc[mf_][nf_][4];
    #pragma unroll
    for (int i = 0; i < mf_; i++)
        #pragma unroll
        for (int j = 0; j < nf_; j++)
            #pragma unroll
            for (int r = 0; r < 4; r++) acc[i][j][r] = 0.0f;

    auto issue = [&](int st, int k0) {
        float* as = As + st * ASZ;
        float* ws = Ws + st * WSZ;
        {
            int r = tid >> 1, c = (tid & 1) * 4;
            cpasync16(&as[r * 12 + c], &g_Z[(size_t)(m0 + r) * DIN + k0 + c]);
        }
        if (BN == 128) {
            int n = tid >> 1, c = (tid & 1) * 4;
            cpasync16(&ws[n * 12 + c], &Wc[n * DIN + k0 + c]);
        } else {
            if (tid < 128) {
                int n = tid >> 1, c = (tid & 1) * 4;
                cpasync16(&ws[n * 12 + c], &Wc[n * DIN + k0 + c]);
            }
        }
        cp_commit();
    };

    constexpr int NT = DIN / BK;   // 48
    issue(0, 0); issue(1, BK);

    int st = 0;
    for (int kt = 0; kt < NT; kt++) {
        cp_wait<STAGES - 2>();
        __syncthreads();
        const float* as = As + st * ASZ;
        const float* ws = Ws + st * WSZ;

        float a[mf_][4];
        #pragma unroll
        for (int mf = 0; mf < mf_; mf++) {
            int row = warp_m + mf * 16 + g4;
            a[mf][0] = as[ row      * 12 + t4    ];
            a[mf][1] = as[(row + 8) * 12 + t4    ];
            a[mf][2] = as[ row      * 12 + t4 + 4];
            a[mf][3] = as[(row + 8) * 12 + t4 + 4];
        }
        #pragma unroll
        for (int nf = 0; nf < nf_; nf++) {
            int col = warp_n + nf * 8 + g4;
            float b0 = ws[col * 12 + t4    ];
            float b1 = ws[col * 12 + t4 + 4];
            #pragma unroll
            for (int mf = 0; mf < mf_; mf++)
                mma_tf32(acc[mf][nf], a[mf][0], a[mf][1], a[mf][2], a[mf][3], b0, b1);
        }

        if (kt + STAGES - 1 < NT) issue((kt + STAGES - 1) % STAGES, (kt + STAGES - 1) * BK);
        else cp_commit();
        st = (st + 1 == STAGES) ? 0 : st + 1;
    }

    #pragma unroll
    for (int mf = 0; mf < mf_; mf++) {
        #pragma unroll
        for (int nf = 0; nf < nf_; nf++) {
            #pragma unroll
            for (int half = 0; half < 2; half++) {
                int row = m0 + warp_m + mf * 16 + g4 + half * 8;
                #pragma unroll
                for (int e = 0; e < 2; e++) {
                    int o = warp_n + nf * 8 + 2 * t4 + e;
                    float v = acc[mf][nf][half * 2 + e];
                    if (WHICH == 1) {
                        float val = sigm(v + g_b1s[o]);
                        if (o < Uu) g_XRH[row * Uu + o] = val * hx[row * Uu + o];
                        else        g_Ug [row * Uu + o - Uu] = val;
                    } else {
                        float c = tanhf(v + g_bcs[o]);
                        float u = g_Ug[row * Uu + o];
                        float h = hx[row * Uu + o];
                        out[row * Uu + o] = u * h + (1.0f - u) * c;
                    }
                }
            }
        }
    }
}

// ------------------------------ launch -------------------------------------
extern "C" void kernel_launch(void* const* d_in, const int* in_sizes, int n_in,
                              void* d_out, int out_size) {
    (void)in_sizes; (void)n_in; (void)out_size;
    const float* logits = (const float*)d_in[0];
    const float* u_noise = (const float*)d_in[1];
    const float* inputs = (const float*)d_in[2];
    const float* hx = (const float*)d_in[3];
    const float* W0 = (const float*)d_in[4];
    const float* b0 = (const float*)d_in[5];
    const float* W1 = (const float*)d_in[6];
    const float* b1 = (const float*)d_in[7];
    const float* Wc0 = (const float*)d_in[8];
    const float* bc0 = (const float*)d_in[9];
    const float* Wc1 = (const float*)d_in[10];
    const float* bc1 = (const float*)d_in[11];
    float* out = (float*)d_out;

    k_prep<<<64, 256>>>(W0, b0, W1, b1, Wc0, bc0, Wc1, bc1);
    k_adj<<<dim3(Nn, Bb), 256>>>((const float4*)logits, (const float4*)u_noise);
    k_colsum<<<dim3(Nn / 256, Bb), 256>>>();
    k_buildX1<<<(Mrows * 32) / 256, 256>>>(inputs, hx);
    k_gemm_tc<1><<<dim3(Nn / 128, 2, Bb), 256>>>();
    k_buildZ1<<<(Mrows * 32) / 256, 256>>>();
    k_wgemm<1><<<Mrows / 128, 256>>>(hx, out);
    k_gemm_tc<2><<<dim3(Nn / 128, 2, Bb), 256>>>();
    k_buildZ2<<<(Mrows * 32) / 256, 256>>>(inputs);
    k_wgemm<2><<<Mrows / 128, 256>>>(hx, out);
}

// round 5
// speedup vs baseline: 2.4487x; 1.1521x over previous
#include <cuda_runtime.h>
#include <math.h>

// ---------------------------------------------------------------------------
// GRELEN: gumbel-softmax adjacency + 2x diffusion-GCN GRU cell
// B=16, N=1024, U=64, K=2  (reference stacks [x, Ax, Ax] due to its loop quirk)
// R5: fused Z dataflow (no P/Q buffers, no Z-builder kernels), RNA-rounded
//     producers, paired-stage cp.async big GEMM, parallel colsum.
// ---------------------------------------------------------------------------

namespace {
constexpr int Bb   = 16;
constexpr int Nn   = 1024;
constexpr int Uu   = 64;
constexpr int DU   = 128;   // 2U
constexpr int DIN  = 384;   // 2U*(K+1)
constexpr int Mrows = Bb * Nn;       // 16384
constexpr float EPSc = 1e-10f;
}

// ------------------------------ scratch ------------------------------------
__device__ float g_adj[(size_t)Bb * Nn * Nn];   // 64 MB (tf32-rounded)
__device__ float g_rowsum[Mrows];
__device__ float g_cpart[4][Mrows];             // colsum partials
__device__ float g_dinv0[Mrows];
__device__ float g_dinv1[Mrows];
__device__ float g_X1 [Mrows * DU];             // [xin | h] tf32-rounded
__device__ float g_XRH[Mrows * Uu];             // r*h tf32-rounded
__device__ float g_Ug [Mrows * Uu];             // update gate u
__device__ float g_Z  [(size_t)Mrows * DIN];    // shared Z1 -> Z2 staging
__device__ float g_W1cat[DU * DIN];
__device__ float g_Wccat[Uu * DIN];
__device__ float g_b1s[DU];
__device__ float g_bcs[Uu];

__device__ __forceinline__ float4 ld4(const float* p) { return *reinterpret_cast<const float4*>(p); }
__device__ __forceinline__ void   st4(float* p, float4 v) { *reinterpret_cast<float4*>(p) = v; }
__device__ __forceinline__ float sigm(float x) { return 1.0f / (1.0f + expf(-x)); }

__device__ __forceinline__ float to_tf32(float x) {
    unsigned u;
    asm("cvt.rna.tf32.f32 %0, %1;" : "=r"(u) : "f"(x));
    return __uint_as_float(u);
}
__device__ __forceinline__ float4 to_tf32_4(float4 v) {
    v.x = to_tf32(v.x); v.y = to_tf32(v.y); v.z = to_tf32(v.z); v.w = to_tf32(v.w);
    return v;
}

__device__ __forceinline__ void cpasync16(float* dst_smem, const float* src) {
    unsigned d = (unsigned)__cvta_generic_to_shared(dst_smem);
    asm volatile("cp.async.cg.shared.global [%0], [%1], 16;\n" :: "r"(d), "l"(src));
}
__device__ __forceinline__ void cp_commit() {
    asm volatile("cp.async.commit_group;\n" ::: "memory");
}
template <int N>
__device__ __forceinline__ void cp_wait() {
    asm volatile("cp.async.wait_group %0;\n" :: "n"(N) : "memory");
}

__device__ __forceinline__ void mma_tf32(float (&d)[4], const float a0, const float a1,
                                         const float a2, const float a3,
                                         const float b0, const float b1) {
    asm volatile(
        "mma.sync.aligned.m16n8k8.row.col.f32.tf32.tf32.f32 "
        "{%0,%1,%2,%3}, {%4,%5,%6,%7}, {%8,%9}, {%0,%1,%2,%3};\n"
        : "+f"(d[0]), "+f"(d[1]), "+f"(d[2]), "+f"(d[3])
        : "r"(__float_as_uint(a0)), "r"(__float_as_uint(a1)),
          "r"(__float_as_uint(a2)), "r"(__float_as_uint(a3)),
          "r"(__float_as_uint(b0)), "r"(__float_as_uint(b1)));
}

// ------------------------------ weight folding (tf32-rounded) --------------
__global__ void k_prep(const float* __restrict__ W0, const float* __restrict__ b0,
                       const float* __restrict__ W1, const float* __restrict__ b1,
                       const float* __restrict__ Wc0, const float* __restrict__ bc0,
                       const float* __restrict__ Wc1, const float* __restrict__ bc1) {
    int t = blockIdx.x * blockDim.x + threadIdx.x;
    int stride = gridDim.x * blockDim.x;
    for (int idx = t; idx < DU * DIN; idx += stride) {
        int o = idx / DIN, k = idx % DIN;
        float v;
        if (k < DU)            v = W0[o*DIN + 3*k]     + W1[o*DIN + 3*k];
        else if (k < 2*DU)   { int f = k - DU;   v = W0[o*DIN + 3*f+1] + W0[o*DIN + 3*f+2]; }
        else                 { int f = k - 2*DU; v = W1[o*DIN + 3*f+1] + W1[o*DIN + 3*f+2]; }
        g_W1cat[idx] = to_tf32(v);
    }
    for (int idx = t; idx < Uu * DIN; idx += stride) {
        int o = idx / DIN, k = idx % DIN;
        float v;
        if (k < DU)            v = Wc0[o*DIN + 3*k]     + Wc1[o*DIN + 3*k];
        else if (k < 2*DU)   { int f = k - DU;   v = Wc0[o*DIN + 3*f+1] + Wc0[o*DIN + 3*f+2]; }
        else                 { int f = k - 2*DU; v = Wc1[o*DIN + 3*f+1] + Wc1[o*DIN + 3*f+2]; }
        g_Wccat[idx] = to_tf32(v);
    }
    if (t < DU) g_b1s[t] = b0[t] + b1[t];
    if (t < Uu) g_bcs[t] = bc0[t] + bc1[t];
}

// ------------------------------ adjacency + row sums -----------------------
__global__ void k_adj(const float4* __restrict__ logits4, const float4* __restrict__ un4) {
    int b = blockIdx.y, i = blockIdx.x, t = threadIdx.x;
    size_t base4 = (size_t)(b * Nn + i) * (Nn / 2);
    float2* adj2 = reinterpret_cast<float2*>(g_adj + (size_t)(b * Nn + i) * Nn);
    float s = 0.0f;
    #pragma unroll
    for (int j = t; j < Nn / 2; j += 256) {
        float4 l = logits4[base4 + j];
        float4 u = un4[base4 + j];
        float t0a = EPSc - __logf(u.x + EPSc), t1a = EPSc - __logf(u.y + EPSc);
        float t0b = EPSc - __logf(u.z + EPSc), t1b = EPSc - __logf(u.w + EPSc);
        float za = 2.0f * ((l.x - l.y) + __logf(t1a) - __logf(t0a));
        float zb = 2.0f * ((l.z - l.w) + __logf(t1b) - __logf(t0b));
        float pa = to_tf32(__fdividef(1.0f, 1.0f + __expf(-za)));
        float pb = to_tf32(__fdividef(1.0f, 1.0f + __expf(-zb)));
        adj2[j] = make_float2(pa, pb);
        s += pa + pb;
    }
    #pragma unroll
    for (int o = 16; o; o >>= 1) s += __shfl_down_sync(0xffffffffu, s, o);
    __shared__ float red[8];
    if ((t & 31) == 0) red[t >> 5] = s;
    __syncthreads();
    if (t == 0) {
        float tot = 0.0f;
        #pragma unroll
        for (int w = 0; w < 8; w++) tot += red[w];
        g_rowsum[b * Nn + i] = tot;
    }
}

// ------------------------------ column sums (4 partials) -------------------
__global__ void k_colsum_part() {
    int b = blockIdx.y, q = blockIdx.z;
    int j = blockIdx.x * 256 + threadIdx.x;
    size_t base = (size_t)b * Nn * Nn + (size_t)q * (Nn / 4) * Nn + j;
    float s = 0.0f;
    #pragma unroll 8
    for (int i = 0; i < Nn / 4; i++) s += g_adj[base + (size_t)i * Nn];
    g_cpart[q][b * Nn + j] = s;
}

__global__ void k_dinv() {
    int i = blockIdx.x * 256 + threadIdx.x;
    float cs = g_cpart[0][i] + g_cpart[1][i] + g_cpart[2][i] + g_cpart[3][i];
    g_dinv0[i] = 1.0f / (cs + 1.0f);
    g_dinv1[i] = 1.0f / (g_rowsum[i] + 1.0f);
}

// ------------------------------ X1 = [xin | h] (rounded) + Z chunk0 --------
__global__ void k_buildX1(const float* __restrict__ inp, const float* __restrict__ hx) {
    int idx = blockIdx.x * 256 + threadIdx.x;    // Mrows * 32 float4s
    int f4 = idx & 31;
    int row = idx >> 5;
    float4 v = (f4 < 16) ? ld4(&inp[row * Uu + f4 * 4]) : ld4(&hx[row * Uu + (f4 - 16) * 4]);
    v = to_tf32_4(v);
    st4(&g_X1[row * DU + f4 * 4], v);
    st4(&g_Z[(size_t)row * DIN + f4 * 4], v);
}

// ------------------------------ big batched GEMM (tf32, paired cp.async) ---
// PHASE 1: rows of Z <- dinv*(A(T)@X1 + X1).  PHASE 2: <- dinv*(A(T)@XRH + XRH)
// BM=128, BK=8, 4 stages consumed/issued in pairs (16-deep per commit group).
template <int PHASE>
__global__ __launch_bounds__(256) void k_gemm_tc() {
    constexpr int BN = (PHASE == 1) ? DU : Uu;
    constexpr int BM = 128, BK = 8, STAGES = 4;
    constexpr int ASZ = 1536;                  // max(128*12, 8*136)
    constexpr int BSTR = BN + 8;               // 136 or 72
    constexpr int BSZ = BK * BSTR;
    constexpr int wn_ = (BN == 128) ? 4 : 2;
    constexpr int wm_ = 8 / wn_;
    constexpr int mf_ = (BM / wm_) / 16;       // 4 or 2
    constexpr int nf_ = (BN / wn_) / 8;        // 4
    // Z column base for this phase/trans: P1:128 Q1:256 P2:192 Q2:320
    const int b = blockIdx.z, trans = blockIdx.y;
    const int m0 = blockIdx.x * BM;
    const int zcol0 = (PHASE == 1) ? (trans ? 256 : 128) : (trans ? 320 : 192);

    const float* A = g_adj + (size_t)b * Nn * Nn;
    const float* X = ((PHASE == 1) ? g_X1 : g_XRH) + (size_t)b * Nn * BN;
    const float* dinv = (trans ? g_dinv1 : g_dinv0);

    __shared__ float As[STAGES * ASZ];
    __shared__ float Bs[STAGES * BSZ];

    const int tid  = threadIdx.x;
    const int w    = tid >> 5;
    const int lane = tid & 31;
    const int g4   = lane >> 2;
    const int t4   = lane & 3;
    const int warp_m = (w % wm_) * (BM / wm_);
    const int warp_n = (w / wm_) * (BN / wn_);

    float acc[mf_][nf_][4];
    #pragma unroll
    for (int i = 0; i < mf_; i++)
        #pragma unroll
        for (int j = 0; j < nf_; j++)
            #pragma unroll
            for (int r = 0; r < 4; r++) acc[i][j][r] = 0.0f;

    auto issue1 = [&](int st, int k0) {     // one stage, no commit
        float* as = As + st * ASZ;
        float* bs = Bs + st * BSZ;
        if (!trans) {
            int r = tid >> 1, c = (tid & 1) * 4;                 // [m][12]
            cpasync16(&as[r * 12 + c], &A[(size_t)(m0 + r) * Nn + k0 + c]);
        } else {
            int k = tid >> 5, c = (tid & 31) * 4;                // [k][136]
            cpasync16(&as[k * 136 + c], &A[(size_t)(k0 + k) * Nn + m0 + c]);
        }
        if (BN == 128) {
            int k = tid >> 5, c = (tid & 31) * 4;
            cpasync16(&bs[k * BSTR + c], &X[(k0 + k) * BN + c]);
        } else if (tid < 128) {
            int k = tid >> 4, c = (tid & 15) * 4;
            cpasync16(&bs[k * BSTR + c], &X[(k0 + k) * BN + c]);
        }
    };
    auto issuePair = [&](int pair, int k0) { // stages (pair&1)*2, +1; one group
        issue1((pair & 1) * 2,     k0);
        issue1((pair & 1) * 2 + 1, k0 + BK);
        cp_commit();
    };

    constexpr int NP = Nn / (2 * BK);   // 64 pairs
    issuePair(0, 0);
    issuePair(1, 2 * BK);

    for (int t = 0; t < NP; t++) {
        cp_wait<1>();
        __syncthreads();
        #pragma unroll
        for (int sub = 0; sub < 2; sub++) {
            const int st = (t & 1) * 2 + sub;
            const float* as = As + st * ASZ;
            const float* bs = Bs + st * BSZ;
            float a[mf_][4];
            if (!trans) {
                #pragma unroll
                for (int mf = 0; mf < mf_; mf++) {
                    int row = warp_m + mf * 16 + g4;
                    a[mf][0] = as[ row      * 12 + t4    ];
                    a[mf][1] = as[(row + 8) * 12 + t4    ];
                    a[mf][2] = as[ row      * 12 + t4 + 4];
                    a[mf][3] = as[(row + 8) * 12 + t4 + 4];
                }
            } else {
                #pragma unroll
                for (int mf = 0; mf < mf_; mf++) {
                    int row = warp_m + mf * 16 + g4;
                    a[mf][0] = as[ t4      * 136 + row    ];
                    a[mf][1] = as[ t4      * 136 + row + 8];
                    a[mf][2] = as[(t4 + 4) * 136 + row    ];
                    a[mf][3] = as[(t4 + 4) * 136 + row + 8];
                }
            }
            #pragma unroll
            for (int nf = 0; nf < nf_; nf++) {
                int col = warp_n + nf * 8 + g4;
                float b0 = bs[ t4      * BSTR + col];
                float b1 = bs[(t4 + 4) * BSTR + col];
                #pragma unroll
                for (int mf = 0; mf < mf_; mf++)
                    mma_tf32(acc[mf][nf], a[mf][0], a[mf][1], a[mf][2], a[mf][3], b0, b1);
            }
        }
        if (t + 2 < NP) issuePair(t + 2, (t + 2) * 2 * BK);
        else cp_commit();
    }

    // epilogue: Z[row, zcol0+col] = rna(dinv[row]*(acc + X[row,col]))
    #pragma unroll
    for (int mf = 0; mf < mf_; mf++) {
        #pragma unroll
        for (int half = 0; half < 2; half++) {
            int rloc = warp_m + mf * 16 + g4 + half * 8;
            int rglob = b * Nn + m0 + rloc;
            float d = dinv[rglob];
            #pragma unroll
            for (int nf = 0; nf < nf_; nf++) {
                int cc = warp_n + nf * 8 + 2 * t4;
                float2 x = *reinterpret_cast<const float2*>(&X[(size_t)(m0 + rloc) * BN + cc]);
                float v0 = to_tf32(d * (acc[mf][nf][half * 2 + 0] + x.x));
                float v1 = to_tf32(d * (acc[mf][nf][half * 2 + 1] + x.y));
                *reinterpret_cast<float2*>(&g_Z[(size_t)rglob * DIN + zcol0 + cc]) =
                    make_float2(v0, v1);
            }
        }
    }
}

// ------------------------------ weight GEMMs (tf32, cp.async x3) -----------
// WHICH=1: sigmoid(Z @ W1cat^T + b1s) -> XRH=r*h (also Z[:,64:128]), Ug.
// WHICH=2: tanh(Z @ Wccat^T + bcs) -> out = u*h + (1-u)*c.
template <int WHICH>
__global__ __launch_bounds__(256) void k_wgemm(const float* __restrict__ hx,
                                               float* __restrict__ out) {
    constexpr int BN = (WHICH == 1) ? DU : Uu;
    constexpr int BM = 128, BK = 8, STAGES = 3;
    constexpr int ASZ = BM * 12;
    constexpr int WSZ = BN * 12;
    constexpr int wn_ = (BN == 128) ? 4 : 2;
    constexpr int wm_ = 8 / wn_;
    constexpr int mf_ = (BM / wm_) / 16;
    constexpr int nf_ = (BN / wn_) / 8;

    const int m0 = blockIdx.x * BM;
    const float* Wc = (WHICH == 1) ? g_W1cat : g_Wccat;

    __shared__ float As[STAGES * ASZ];
    __shared__ float Ws[STAGES * WSZ];

    const int tid  = threadIdx.x;
    const int w    = tid >> 5;
    const int lane = tid & 31;
    const int g4   = lane >> 2;
    const int t4   = lane & 3;
    const int warp_m = (w % wm_) * (BM / wm_);
    const int warp_n = (w / wm_) * (BN / wn_);

    float acc[mf_][nf_][4];
    #pragma unroll
    for (int i = 0; i < mf_; i++)
        #pragma unroll
        for (int j = 0; j < nf_; j++)
            #pragma unroll
            for (int r = 0; r < 4; r++) acc[i][j][r] = 0.0f;

    auto issue = [&](int st, int k0) {
        float* as = As + st * ASZ;
        float* ws = Ws + st * WSZ;
        {
            int r = tid >> 1, c = (tid & 1) * 4;
            cpasync16(&as[r * 12 + c], &g_Z[(size_t)(m0 + r) * DIN + k0 + c]);
        }
        if (BN == 128) {
            int n = tid >> 1, c = (tid & 1) * 4;
            cpasync16(&ws[n * 12 + c], &Wc[n * DIN + k0 + c]);
        } else if (tid < 128) {
            int n = tid >> 1, c = (tid & 1) * 4;
            cpasync16(&ws[n * 12 + c], &Wc[n * DIN + k0 + c]);
        }
        cp_commit();
    };

    constexpr int NT = DIN / BK;   // 48
    issue(0, 0); issue(1, BK);

    int st = 0;
    for (int kt = 0; kt < NT; kt++) {
        cp_wait<STAGES - 2>();
        __syncthreads();
        const float* as = As + st * ASZ;
        const float* ws = Ws + st * WSZ;

        float a[mf_][4];
        #pragma unroll
        for (int mf = 0; mf < mf_; mf++) {
            int row = warp_m + mf * 16 + g4;
            a[mf][0] = as[ row      * 12 + t4    ];
            a[mf][1] = as[(row + 8) * 12 + t4    ];
            a[mf][2] = as[ row      * 12 + t4 + 4];
            a[mf][3] = as[(row + 8) * 12 + t4 + 4];
        }
        #pragma unroll
        for (int nf = 0; nf < nf_; nf++) {
            int col = warp_n + nf * 8 + g4;
            float b0 = ws[col * 12 + t4    ];
            float b1 = ws[col * 12 + t4 + 4];
            #pragma unroll
            for (int mf = 0; mf < mf_; mf++)
                mma_tf32(acc[mf][nf], a[mf][0], a[mf][1], a[mf][2], a[mf][3], b0, b1);
        }

        if (kt + STAGES - 1 < NT) issue((kt + STAGES - 1) % STAGES, (kt + STAGES - 1) * BK);
        else cp_commit();
        st = (st + 1 == STAGES) ? 0 : st + 1;
    }

    #pragma unroll
    for (int mf = 0; mf < mf_; mf++) {
        #pragma unroll
        for (int nf = 0; nf < nf_; nf++) {
            #pragma unroll
            for (int half = 0; half < 2; half++) {
                int row = m0 + warp_m + mf * 16 + g4 + half * 8;
                #pragma unroll
                for (int e = 0; e < 2; e++) {
                    int o = warp_n + nf * 8 + 2 * t4 + e;
                    float v = acc[mf][nf][half * 2 + e];
                    if (WHICH == 1) {
                        float val = sigm(v + g_b1s[o]);
                        if (o < Uu) {
                            float rh = to_tf32(val * hx[row * Uu + o]);
                            g_XRH[row * Uu + o] = rh;
                            g_Z[(size_t)row * DIN + Uu + o] = rh;   // Z2 chunk0 upper half
                        } else {
                            g_Ug[row * Uu + o - Uu] = val;
                        }
                    } else {
                        float c = tanhf(v + g_bcs[o]);
                        float u = g_Ug[row * Uu + o];
                        float h = hx[row * Uu + o];
                        out[row * Uu + o] = u * h + (1.0f - u) * c;
                    }
                }
            }
        }
    }
}

// ------------------------------ launch -------------------------------------
extern "C" void kernel_launch(void* const* d_in, const int* in_sizes, int n_in,
                              void* d_out, int out_size) {
    (void)in_sizes; (void)n_in; (void)out_size;
    const float* logits = (const float*)d_in[0];
    const float* u_noise = (const float*)d_in[1];
    const float* inputs = (const float*)d_in[2];
    const float* hx = (const float*)d_in[3];
    const float* W0 = (const float*)d_in[4];
    const float* b0 = (const float*)d_in[5];
    const float* W1 = (const float*)d_in[6];
    const float* b1 = (const float*)d_in[7];
    const float* Wc0 = (const float*)d_in[8];
    const float* bc0 = (const float*)d_in[9];
    const float* Wc1 = (const float*)d_in[10];
    const float* bc1 = (const float*)d_in[11];
    float* out = (float*)d_out;

    k_prep<<<64, 256>>>(W0, b0, W1, b1, Wc0, bc0, Wc1, bc1);
    k_adj<<<dim3(Nn, Bb), 256>>>((const float4*)logits, (const float4*)u_noise);
    k_colsum_part<<<dim3(Nn / 256, Bb, 4), 256>>>();
    k_dinv<<<Mrows / 256, 256>>>();
    k_buildX1<<<(Mrows * 32) / 256, 256>>>(inputs, hx);
    k_gemm_tc<1><<<dim3(Nn / 128, 2, Bb), 256>>>();
    k_wgemm<1><<<Mrows / 128, 256>>>(hx, out);
    k_gemm_tc<2><<<dim3(Nn / 128, 2, Bb), 256>>>();
    k_wgemm<2><<<Mrows / 128, 256>>>(hx, out);
}